// round 1
// baseline (speedup 1.0000x reference)
#include <cuda_runtime.h>

#define D_MODEL 1024
#define D_FF    2048
#define N_EXP   8
#define MAX_T   8192

// ---------------- routing / scratch state (static device globals) -------------
__device__ int   g_cnt[N_EXP];
__device__ int   g_off[N_EXP + 1];
__device__ int   g_cur[N_EXP];
__device__ int   g_e0[MAX_T], g_e1[MAX_T];
__device__ float g_w0[MAX_T], g_w1[MAX_T];
__device__ int   g_tok[2 * MAX_T];
__device__ float g_gw [2 * MAX_T];
__device__ float g_h  [2 * MAX_T * D_FF];   // routed layer-1 activations (compact rows)
__device__ float g_hs [MAX_T * D_FF];       // shared-expert layer-1 activations

// ---------------- tiny kernels -----------------------------------------------
__global__ void zero_counts_kernel() {
    if (threadIdx.x < N_EXP) g_cnt[threadIdx.x] = 0;
}

// one warp per token: 8 logits -> softmax -> top2 -> renormalized weights
__global__ void gate_kernel(const float* __restrict__ x,
                            const float* __restrict__ gw, int T) {
    int warp = threadIdx.x >> 5;
    int lane = threadIdx.x & 31;
    int t = blockIdx.x * 8 + warp;
    if (t >= T) return;
    const float* xt = x + (long)t * D_MODEL;
    float acc[N_EXP];
#pragma unroll
    for (int e = 0; e < N_EXP; e++) acc[e] = 0.f;
    for (int d = lane; d < D_MODEL; d += 32) {
        float xv = xt[d];
#pragma unroll
        for (int e = 0; e < N_EXP; e++) acc[e] += xv * gw[e * D_MODEL + d];
    }
#pragma unroll
    for (int e = 0; e < N_EXP; e++) {
#pragma unroll
        for (int o = 16; o; o >>= 1)
            acc[e] += __shfl_xor_sync(0xffffffffu, acc[e], o);
    }
    if (lane == 0) {
        int e0 = 0;
#pragma unroll
        for (int e = 1; e < N_EXP; e++) if (acc[e] > acc[e0]) e0 = e;
        int e1 = (e0 == 0) ? 1 : 0;
#pragma unroll
        for (int e = 0; e < N_EXP; e++)
            if (e != e0 && acc[e] > acc[e1]) e1 = e;
        float s1 = expf(acc[e1] - acc[e0]);      // s0 = 1
        float inv = 1.f / (1.f + s1);
        g_e0[t] = e0; g_e1[t] = e1;
        g_w0[t] = inv; g_w1[t] = s1 * inv;
        atomicAdd(&g_cnt[e0], 1);
        atomicAdd(&g_cnt[e1], 1);
    }
}

__global__ void offsets_kernel() {
    int o = 0;
    for (int e = 0; e < N_EXP; e++) { g_off[e] = o; g_cur[e] = o; o += g_cnt[e]; }
    g_off[N_EXP] = o;
}

__global__ void scatter_kernel(int T) {
    int t = blockIdx.x * blockDim.x + threadIdx.x;
    if (t >= T) return;
    int e0 = g_e0[t], e1 = g_e1[t];
    int p0 = atomicAdd(&g_cur[e0], 1);
    g_tok[p0] = t; g_gw[p0] = g_w0[t];
    int p1 = atomicAdd(&g_cur[e1], 1);
    g_tok[p1] = t; g_gw[p1] = g_w1[t];
}

// ---------------- tiled GEMM:  C = [relu]( A_rows @ B^T + bias ) -------------
// A: [*, K] row-major (rows selected per flags), B: [N, K] row-major.
// EXPERT:      blockIdx.z selects expert; rows are the compact segment
//              [g_off[e], g_off[e]+g_cnt[e]); B/bias get per-expert strides.
// GATHER_A:    A row = g_tok[r] (token gather), else A row = r.
// ATOMIC_OUT:  C row = token g_tok[r], value scaled by g_gw[r], atomicAdd.
#define BM 128
#define BN 128
#define BK 8

template<bool EXPERT, bool GATHER_A, bool RELU, bool ATOMIC_OUT>
__global__ __launch_bounds__(256, 2)
void gemm_kernel(const float* __restrict__ A,
                 const float* __restrict__ Bb,
                 const float* __restrict__ biasb,
                 float* __restrict__ C,
                 int M, int N, int K,
                 long wstride, int bstride, int ldc) {
    int m_base, m_end;
    const float* B;
    const float* bias;
    if (EXPERT) {
        int e = blockIdx.z;
        int cnt = g_cnt[e];
        if ((int)(blockIdx.y * BM) >= cnt) return;
        int off = g_off[e];
        m_base = off + blockIdx.y * BM;
        m_end  = off + cnt;
        B = Bb + (long)e * wstride;
        bias = biasb + (long)e * bstride;
    } else {
        m_base = blockIdx.y * BM;
        m_end  = M;
        B = Bb; bias = biasb;
    }
    int n0 = blockIdx.x * BN;

    __shared__ __align__(16) float As[BK][BM];
    __shared__ __align__(16) float Bs[BK][BN];
    __shared__ int rowsrc[BM];

    int tid = threadIdx.x;
    int tx = tid & 15;          // 0..15 (N direction)
    int ty = tid >> 4;          // 0..15 (M direction)

    if (GATHER_A) {
        for (int i = tid; i < BM; i += 256) {
            int r = m_base + i;
            rowsrc[i] = (r < m_end) ? g_tok[r] : -1;
        }
        __syncthreads();
    }

    int a_row = tid >> 1;            // 0..127
    int a_seg = (tid & 1) * 4;       // 0 or 4

    long a_src;
    bool a_valid;
    {
        int r = m_base + a_row;
        if (GATHER_A) {
            int tok = rowsrc[a_row];
            a_valid = (tok >= 0);
            a_src = (long)(a_valid ? tok : 0);
        } else {
            a_valid = (r < m_end);
            a_src = (long)(a_valid ? r : 0);
        }
    }
    long b_src = (long)(n0 + a_row);

    float acc[2][2][4][4];
#pragma unroll
    for (int qm = 0; qm < 2; qm++)
#pragma unroll
        for (int qn = 0; qn < 2; qn++)
#pragma unroll
            for (int i = 0; i < 4; i++)
#pragma unroll
                for (int j = 0; j < 4; j++) acc[qm][qn][i][j] = 0.f;

    for (int k0 = 0; k0 < K; k0 += BK) {
        float4 av = make_float4(0.f, 0.f, 0.f, 0.f);
        if (a_valid)
            av = *(const float4*)(A + a_src * (long)K + k0 + a_seg);
        float4 bv = *(const float4*)(B + b_src * (long)K + k0 + a_seg);

        __syncthreads();
        As[a_seg + 0][a_row] = av.x;
        As[a_seg + 1][a_row] = av.y;
        As[a_seg + 2][a_row] = av.z;
        As[a_seg + 3][a_row] = av.w;
        Bs[a_seg + 0][a_row] = bv.x;
        Bs[a_seg + 1][a_row] = bv.y;
        Bs[a_seg + 2][a_row] = bv.z;
        Bs[a_seg + 3][a_row] = bv.w;
        __syncthreads();

        float ar[2][4], br[2][4];
#pragma unroll
        for (int k = 0; k < BK; k++) {
            *(float4*)ar[0] = *(const float4*)&As[k][ty * 4];
            *(float4*)ar[1] = *(const float4*)&As[k][64 + ty * 4];
            *(float4*)br[0] = *(const float4*)&Bs[k][tx * 4];
            *(float4*)br[1] = *(const float4*)&Bs[k][64 + tx * 4];
#pragma unroll
            for (int qm = 0; qm < 2; qm++)
#pragma unroll
                for (int qn = 0; qn < 2; qn++)
#pragma unroll
                    for (int i = 0; i < 4; i++)
#pragma unroll
                        for (int j = 0; j < 4; j++)
                            acc[qm][qn][i][j] += ar[qm][i] * br[qn][j];
        }
    }

    // epilogue
#pragma unroll
    for (int qm = 0; qm < 2; qm++) {
#pragma unroll
        for (int i = 0; i < 4; i++) {
            int r = m_base + qm * 64 + ty * 4 + i;
            if (r >= m_end) continue;
            if (ATOMIC_OUT) {
                int tok = g_tok[r];
                float sc = g_gw[r];
                float* crow = C + (long)tok * ldc;
#pragma unroll
                for (int qn = 0; qn < 2; qn++) {
#pragma unroll
                    for (int j = 0; j < 4; j++) {
                        int cn = n0 + qn * 64 + tx * 4 + j;
                        float v = acc[qm][qn][i][j] + bias[cn];
                        if (RELU) v = fmaxf(v, 0.f);
                        atomicAdd(crow + cn, sc * v);
                    }
                }
            } else {
                float* crow = C + (long)r * ldc;
#pragma unroll
                for (int qn = 0; qn < 2; qn++) {
                    int cn = n0 + qn * 64 + tx * 4;
                    float4 bv4 = *(const float4*)(bias + cn);
                    float4 v;
                    v.x = acc[qm][qn][i][0] + bv4.x;
                    v.y = acc[qm][qn][i][1] + bv4.y;
                    v.z = acc[qm][qn][i][2] + bv4.z;
                    v.w = acc[qm][qn][i][3] + bv4.w;
                    if (RELU) {
                        v.x = fmaxf(v.x, 0.f); v.y = fmaxf(v.y, 0.f);
                        v.z = fmaxf(v.z, 0.f); v.w = fmaxf(v.w, 0.f);
                    }
                    *(float4*)(crow + cn) = v;
                }
            }
        }
    }
}

// ---------------- launch ------------------------------------------------------
extern "C" void kernel_launch(void* const* d_in, const int* in_sizes, int n_in,
                              void* d_out, int out_size) {
    const float* x      = (const float*)d_in[0];
    const float* gate_w = (const float*)d_in[1];
    const float* w1     = (const float*)d_in[2];
    const float* b1     = (const float*)d_in[3];
    const float* w2     = (const float*)d_in[4];
    const float* b2     = (const float*)d_in[5];
    const float* ws1    = (const float*)d_in[6];
    const float* bs1    = (const float*)d_in[7];
    const float* ws2    = (const float*)d_in[8];
    const float* bs2    = (const float*)d_in[9];
    float* out = (float*)d_out;

    int T = in_sizes[0] / D_MODEL;          // 8192

    float* hbuf  = nullptr;
    float* hsbuf = nullptr;
    cudaGetSymbolAddress((void**)&hbuf, g_h);
    cudaGetSymbolAddress((void**)&hsbuf, g_hs);

    // routing
    zero_counts_kernel<<<1, 32>>>();
    gate_kernel<<<(T + 7) / 8, 256>>>(x, gate_w, T);
    offsets_kernel<<<1, 1>>>();
    scatter_kernel<<<(T + 255) / 256, 256>>>(T);

    // shared expert path (writes out directly; establishes base before atomics)
    gemm_kernel<false, false, true, false>
        <<<dim3(D_FF / BN, T / BM, 1), 256>>>(
            x, ws1, bs1, hsbuf, T, D_FF, D_MODEL, 0, 0, D_FF);
    gemm_kernel<false, false, false, false>
        <<<dim3(D_MODEL / BN, T / BM, 1), 256>>>(
            hsbuf, ws2, bs2, out, T, D_MODEL, D_FF, 0, 0, D_MODEL);

    // routed experts
    gemm_kernel<true, true, true, false>
        <<<dim3(D_FF / BN, T / BM, N_EXP), 256>>>(
            x, w1, b1, hbuf, 0, D_FF, D_MODEL,
            (long)D_FF * D_MODEL, D_FF, D_FF);
    gemm_kernel<true, false, false, true>
        <<<dim3(D_MODEL / BN, T / BM, N_EXP), 256>>>(
            hbuf, w2, b2, out, 0, D_MODEL, D_FF,
            (long)D_MODEL * D_FF, D_MODEL, D_MODEL);
}

// round 4
// speedup vs baseline: 3.3500x; 3.3500x over previous
#include <cuda_runtime.h>
#include <cstdint>

#define D_MODEL 1024
#define D_FF    2048
#define N_EXP   8
#define MAX_T   8192

#define BM 128
#define BN 256
#define BK 32                                  // floats of K per stage chunk
#define STAGES 3
#define A_BYTES (BM * BK * 4)                  // 16384
#define B_BYTES (BN * BK * 4)                  // 32768
#define STAGE_BYTES (A_BYTES + B_BYTES)        // 49152
#define SMEM_ALLOC (STAGES * STAGE_BYTES + 128)

// ---------------- device globals ----------------------------------------------
__device__ int   g_cnt[N_EXP];
__device__ int   g_off[N_EXP + 1];
__device__ int   g_cur[N_EXP];
__device__ int   g_e0[MAX_T], g_e1[MAX_T];
__device__ float g_w0[MAX_T], g_w1[MAX_T];
__device__ int   g_tok[2 * MAX_T];
__device__ float g_gw [2 * MAX_T];
__device__ float g_h  [2 * MAX_T * D_FF];       // routed L1 activations
__device__ float g_hs [MAX_T * D_FF];           // shared L1 activations
__device__ float g_xr [MAX_T * D_MODEL];        // tf32-rounded x
__device__ float g_w1r[N_EXP * D_FF * D_MODEL];
__device__ float g_w2r[N_EXP * D_MODEL * D_FF];
__device__ float g_ws1r[D_FF * D_MODEL];
__device__ float g_ws2r[D_MODEL * D_FF];

// ---------------- helpers -------------------------------------------------------
__device__ __forceinline__ uint32_t smem_u32(const void* p) {
    uint32_t a;
    asm("{ .reg .u64 t; cvta.to.shared.u64 t, %1; cvt.u32.u64 %0, t; }" : "=r"(a) : "l"(p));
    return a;
}
__device__ __forceinline__ float rtf32(float x) {
    float y; asm("cvt.rna.tf32.f32 %0, %1;" : "=f"(y) : "f"(x)); return y;
}
__device__ __forceinline__ uint32_t lds32(uint32_t a) {
    uint32_t v; asm("ld.shared.b32 %0, [%1];" : "=r"(v) : "r"(a)); return v;
}

#define CP_ASYNC16(dst, src, sz) \
    asm volatile("cp.async.cg.shared.global [%0], [%1], 16, %2;" \
                 :: "r"(dst), "l"(src), "r"(sz))
#define CP_COMMIT() asm volatile("cp.async.commit_group;" ::: "memory")
#define CP_WAIT1()  asm volatile("cp.async.wait_group 1;" ::: "memory")

// smem byte address of element (row, k) within a tile region (128B rows,
// 16B-chunk XOR swizzle keyed on row%8) — matches the cp.async store pattern.
__device__ __forceinline__ uint32_t tile_addr(int row, int k) {
    return (uint32_t)(row * 128) + (((uint32_t)(k * 4)) ^ (((uint32_t)(row & 7)) << 4));
}

__device__ __forceinline__ void mma_tf32(float* c, const uint32_t* a, const uint32_t* b) {
    asm volatile(
        "mma.sync.aligned.m16n8k8.row.col.f32.tf32.tf32.f32 "
        "{%0,%1,%2,%3}, {%4,%5,%6,%7}, {%8,%9}, {%0,%1,%2,%3};"
        : "+f"(c[0]), "+f"(c[1]), "+f"(c[2]), "+f"(c[3])
        : "r"(a[0]), "r"(a[1]), "r"(a[2]), "r"(a[3]), "r"(b[0]), "r"(b[1]));
}

// ---------------- small kernels -------------------------------------------------
__global__ void zero_counts_kernel() {
    if (threadIdx.x < N_EXP) g_cnt[threadIdx.x] = 0;
}

__global__ void round_tf32_kernel(const float4* __restrict__ src,
                                  float4* __restrict__ dst, int n4) {
    int i = blockIdx.x * blockDim.x + threadIdx.x;
    if (i < n4) {
        float4 v = src[i];
        v.x = rtf32(v.x); v.y = rtf32(v.y); v.z = rtf32(v.z); v.w = rtf32(v.w);
        dst[i] = v;
    }
}

__global__ void gate_kernel(const float* __restrict__ x,
                            const float* __restrict__ gw, int T) {
    int warp = threadIdx.x >> 5;
    int lane = threadIdx.x & 31;
    int t = blockIdx.x * 8 + warp;
    if (t >= T) return;
    const float* xt = x + (long)t * D_MODEL;
    float acc[N_EXP];
#pragma unroll
    for (int e = 0; e < N_EXP; e++) acc[e] = 0.f;
    for (int d = lane; d < D_MODEL; d += 32) {
        float xv = xt[d];
#pragma unroll
        for (int e = 0; e < N_EXP; e++) acc[e] += xv * gw[e * D_MODEL + d];
    }
#pragma unroll
    for (int e = 0; e < N_EXP; e++)
#pragma unroll
        for (int o = 16; o; o >>= 1)
            acc[e] += __shfl_xor_sync(0xffffffffu, acc[e], o);
    if (lane == 0) {
        int e0 = 0;
#pragma unroll
        for (int e = 1; e < N_EXP; e++) if (acc[e] > acc[e0]) e0 = e;
        int e1 = (e0 == 0) ? 1 : 0;
#pragma unroll
        for (int e = 0; e < N_EXP; e++)
            if (e != e0 && acc[e] > acc[e1]) e1 = e;
        float s1 = expf(acc[e1] - acc[e0]);
        float inv = 1.f / (1.f + s1);
        g_e0[t] = e0; g_e1[t] = e1;
        g_w0[t] = inv; g_w1[t] = s1 * inv;
        atomicAdd(&g_cnt[e0], 1);
        atomicAdd(&g_cnt[e1], 1);
    }
}

__global__ void offsets_kernel() {
    int o = 0;
    for (int e = 0; e < N_EXP; e++) { g_off[e] = o; g_cur[e] = o; o += g_cnt[e]; }
    g_off[N_EXP] = o;
}

__global__ void scatter_kernel(int T) {
    int t = blockIdx.x * blockDim.x + threadIdx.x;
    if (t >= T) return;
    int p0 = atomicAdd(&g_cur[g_e0[t]], 1);
    g_tok[p0] = t; g_gw[p0] = g_w0[t];
    int p1 = atomicAdd(&g_cur[g_e1[t]], 1);
    g_tok[p1] = t; g_gw[p1] = g_w1[t];
}

// ---------------- tf32 mma.sync GEMM -------------------------------------------
// C = [relu/round]( A_rows @ B^T + bias ); A:[*,K] rows, B:[N,K] row-major fp32.
template<bool EXPERT, bool GATHER_A, bool RELU_ROUND, bool ATOMIC_OUT>
__global__ __launch_bounds__(256, 1)
void mma_gemm_kernel(const float* __restrict__ A,
                     const float* __restrict__ Bb,
                     const float* __restrict__ biasb,
                     float* __restrict__ C,
                     int M, int K, long wstride, int bstride, int ldc) {
    int m_base, m_end;
    const float* Bw;
    const float* bias;
    if (EXPERT) {
        int e = blockIdx.z;
        int cnt = g_cnt[e];
        if ((int)(blockIdx.y * BM) >= cnt) return;
        int off = g_off[e];
        m_base = off + blockIdx.y * BM;
        m_end  = off + cnt;
        Bw = Bb + (long)e * wstride;
        bias = biasb + (long)e * bstride;
    } else {
        m_base = blockIdx.y * BM;
        m_end  = M;
        Bw = Bb; bias = biasb;
    }
    const int n0 = blockIdx.x * BN;
    const int KC = K / BK;

    extern __shared__ char smem_raw[];
    const uint32_t smem = (smem_u32(smem_raw) + 127u) & ~127u;

    const int tid = threadIdx.x;
    const int wid = tid >> 5;
    const int lid = tid & 31;
    const int grp = lid >> 2;          // 0..7
    const int q   = lid & 3;           // 0..3
    const int warp_m = (wid & 1) * 64;
    const int warp_n = (wid >> 1) * 64;

    // ---- gmem load assignments: A 1024 16B segs (4/thr), B 2048 (8/thr) ----
    const int seg = tid & 7;            // 16B seg within 128B row
    const int r8  = tid >> 3;           // 0..31
    int a_srcrow[4];
    uint32_t a_sz[4];
#pragma unroll
    for (int i = 0; i < 4; i++) {
        int row_local = r8 + 32 * i;
        int r = m_base + row_local;
        bool v = (r < m_end);
        int sr;
        if (GATHER_A) sr = v ? g_tok[r] : 0;
        else          sr = v ? r : 0;
        a_srcrow[i] = sr;
        a_sz[i] = v ? 16u : 0u;
    }
    const float* bbase = Bw + (long)(n0 + r8) * K + seg * 4;

    auto load_stage = [&](int s, int chunk) {
        uint32_t aB = smem + s * STAGE_BYTES;
        uint32_t bB = aB + A_BYTES;
        long ko = (long)chunk * BK;
#pragma unroll
        for (int i = 0; i < 4; i++) {
            int row_local = r8 + 32 * i;
            uint32_t dst = aB + tile_addr(row_local, 0) + ((seg * 16u) ^ ((uint32_t)(row_local & 7) << 4)) - (((uint32_t)0) );
            // tile_addr(row,0) gives row*128 ^ swizzle-of-0; recompute cleanly:
            dst = aB + (uint32_t)(row_local * 128) + (((uint32_t)(seg * 16)) ^ (((uint32_t)(row_local & 7)) << 4));
            CP_ASYNC16(dst, A + (long)a_srcrow[i] * K + seg * 4 + ko, a_sz[i]);
        }
#pragma unroll
        for (int j = 0; j < 8; j++) {
            int row_local = r8 + 32 * j;
            uint32_t dst = bB + (uint32_t)(row_local * 128) + (((uint32_t)(seg * 16)) ^ (((uint32_t)(row_local & 7)) << 4));
            CP_ASYNC16(dst, bbase + j * 32L * K + ko, 16u);
        }
    };

    float acc[4][8][4];
#pragma unroll
    for (int mt = 0; mt < 4; mt++)
#pragma unroll
        for (int nt = 0; nt < 8; nt++)
#pragma unroll
            for (int i = 0; i < 4; i++) acc[mt][nt][i] = 0.f;

    // prologue
#pragma unroll
    for (int p = 0; p < STAGES - 1; p++) { load_stage(p, p); CP_COMMIT(); }

    for (int kc = 0; kc < KC; kc++) {
        CP_WAIT1();
        __syncthreads();
        int nc = kc + STAGES - 1;
        if (nc < KC) load_stage(nc % STAGES, nc);
        CP_COMMIT();

        uint32_t aS = smem + (kc % STAGES) * STAGE_BYTES;
        uint32_t bS = aS + A_BYTES;
#pragma unroll
        for (int ks = 0; ks < 4; ks++) {
            const int kq = ks * 8;
            uint32_t afr[4][4], bfr[8][2];
#pragma unroll
            for (int mt = 0; mt < 4; mt++) {
                int r0 = warp_m + mt * 16 + grp;
                afr[mt][0] = lds32(aS + tile_addr(r0,     kq + q));
                afr[mt][1] = lds32(aS + tile_addr(r0 + 8, kq + q));
                afr[mt][2] = lds32(aS + tile_addr(r0,     kq + q + 4));
                afr[mt][3] = lds32(aS + tile_addr(r0 + 8, kq + q + 4));
            }
#pragma unroll
            for (int nt = 0; nt < 8; nt++) {
                int n = warp_n + nt * 8 + grp;
                bfr[nt][0] = lds32(bS + tile_addr(n, kq + q));
                bfr[nt][1] = lds32(bS + tile_addr(n, kq + q + 4));
            }
#pragma unroll
            for (int mt = 0; mt < 4; mt++)
#pragma unroll
                for (int nt = 0; nt < 8; nt++)
                    mma_tf32(acc[mt][nt], afr[mt], bfr[nt]);
        }
    }

    // ---- epilogue ----
#pragma unroll
    for (int mt = 0; mt < 4; mt++) {
#pragma unroll
        for (int half = 0; half < 2; half++) {
            int r = m_base + warp_m + mt * 16 + grp + half * 8;
            if (r >= m_end) continue;
            float sc = 0.f;
            float* crow;
            if (ATOMIC_OUT) {
                int tok = g_tok[r];
                sc = g_gw[r];
                crow = C + (long)tok * ldc;
            } else {
                crow = C + (long)r * ldc;
            }
#pragma unroll
            for (int nt = 0; nt < 8; nt++) {
                int cn = n0 + warp_n + nt * 8 + 2 * q;
                float v0 = acc[mt][nt][half * 2 + 0] + bias[cn];
                float v1 = acc[mt][nt][half * 2 + 1] + bias[cn + 1];
                if (RELU_ROUND) {
                    float2 o;
                    o.x = rtf32(fmaxf(v0, 0.f));
                    o.y = rtf32(fmaxf(v1, 0.f));
                    *(float2*)(crow + cn) = o;
                } else if (ATOMIC_OUT) {
                    atomicAdd(crow + cn + 0, sc * v0);
                    atomicAdd(crow + cn + 1, sc * v1);
                } else {
                    float2 o; o.x = v0; o.y = v1;
                    *(float2*)(crow + cn) = o;
                }
            }
        }
    }
}

// ---------------- launch --------------------------------------------------------
extern "C" void kernel_launch(void* const* d_in, const int* in_sizes, int n_in,
                              void* d_out, int out_size) {
    const float* x      = (const float*)d_in[0];
    const float* gate_w = (const float*)d_in[1];
    const float* w1     = (const float*)d_in[2];
    const float* b1     = (const float*)d_in[3];
    const float* w2     = (const float*)d_in[4];
    const float* b2     = (const float*)d_in[5];
    const float* ws1    = (const float*)d_in[6];
    const float* bs1    = (const float*)d_in[7];
    const float* ws2    = (const float*)d_in[8];
    const float* bs2    = (const float*)d_in[9];
    float* out = (float*)d_out;
    int T = in_sizes[0] / D_MODEL;   // 8192

    float *h, *hs, *xr, *w1r, *w2r, *ws1r, *ws2r;
    cudaGetSymbolAddress((void**)&h,    g_h);
    cudaGetSymbolAddress((void**)&hs,   g_hs);
    cudaGetSymbolAddress((void**)&xr,   g_xr);
    cudaGetSymbolAddress((void**)&w1r,  g_w1r);
    cudaGetSymbolAddress((void**)&w2r,  g_w2r);
    cudaGetSymbolAddress((void**)&ws1r, g_ws1r);
    cudaGetSymbolAddress((void**)&ws2r, g_ws2r);

    cudaFuncSetAttribute(mma_gemm_kernel<false, false, true,  false>,
                         cudaFuncAttributeMaxDynamicSharedMemorySize, SMEM_ALLOC);
    cudaFuncSetAttribute(mma_gemm_kernel<false, false, false, false>,
                         cudaFuncAttributeMaxDynamicSharedMemorySize, SMEM_ALLOC);
    cudaFuncSetAttribute(mma_gemm_kernel<true,  true,  true,  false>,
                         cudaFuncAttributeMaxDynamicSharedMemorySize, SMEM_ALLOC);
    cudaFuncSetAttribute(mma_gemm_kernel<true,  false, false, true >,
                         cudaFuncAttributeMaxDynamicSharedMemorySize, SMEM_ALLOC);

    // tf32 RN pre-rounding (removes mma truncation bias)
    auto launch_round = [&](const float* s, float* d, long n) {
        int n4 = (int)(n / 4);
        round_tf32_kernel<<<(n4 + 255) / 256, 256>>>((const float4*)s, (float4*)d, n4);
    };
    launch_round(x,   xr,   (long)T * D_MODEL);
    launch_round(w1,  w1r,  (long)N_EXP * D_FF * D_MODEL);
    launch_round(w2,  w2r,  (long)N_EXP * D_MODEL * D_FF);
    launch_round(ws1, ws1r, (long)D_FF * D_MODEL);
    launch_round(ws2, ws2r, (long)D_MODEL * D_FF);

    // routing
    zero_counts_kernel<<<1, 32>>>();
    gate_kernel<<<(T + 7) / 8, 256>>>(x, gate_w, T);
    offsets_kernel<<<1, 1>>>();
    scatter_kernel<<<(T + 255) / 256, 256>>>(T);

    // layer 1 (relu + tf32 round into h buffers)
    mma_gemm_kernel<false, false, true, false>
        <<<dim3(D_FF / BN, T / BM, 1), 256, SMEM_ALLOC>>>(
            xr, ws1r, bs1, hs, T, D_MODEL, 0, 0, D_FF);
    mma_gemm_kernel<true, true, true, false>
        <<<dim3(D_FF / BN, 2 * T / BM, N_EXP), 256, SMEM_ALLOC>>>(
            xr, w1r, b1, h, 0, D_MODEL, (long)D_FF * D_MODEL, D_FF, D_FF);

    // layer 2: shared writes base, routed atomically accumulates
    mma_gemm_kernel<false, false, false, false>
        <<<dim3(D_MODEL / BN, T / BM, 1), 256, SMEM_ALLOC>>>(
            hs, ws2r, bs2, out, T, D_FF, 0, 0, D_MODEL);
    mma_gemm_kernel<true, false, false, true>
        <<<dim3(D_MODEL / BN, 2 * T / BM, N_EXP), 256, SMEM_ALLOC>>>(
            h, w2r, b2, out, 0, D_FF, (long)D_MODEL * D_FF, D_MODEL, D_MODEL);
}

// round 5
// speedup vs baseline: 5.9112x; 1.7645x over previous
#include <cuda_runtime.h>
#include <cuda_fp16.h>
#include <cstdint>

#define D_MODEL 1024
#define D_FF    2048
#define N_EXP   8
#define MAX_T   8192

#define BM 128
#define BN 256
#define BK 64                                  // halves of K per stage chunk (128B row)
#define STAGES 3
#define A_BYTES (BM * 128)                     // 16384
#define B_BYTES (BN * 128)                     // 32768
#define STAGE_BYTES (A_BYTES + B_BYTES)        // 49152
#define SMEM_ALLOC (STAGES * STAGE_BYTES + 128)

// ---------------- device globals ----------------------------------------------
__device__ int    g_cnt[N_EXP];
__device__ int    g_off[N_EXP + 1];
__device__ int    g_cur[N_EXP];
__device__ int    g_e0[MAX_T], g_e1[MAX_T];
__device__ float  g_w0[MAX_T], g_w1[MAX_T];
__device__ int    g_tok[2 * MAX_T];
__device__ float  g_gw [2 * MAX_T];
__device__ __half g_h  [2 * MAX_T * D_FF];      // routed L1 activations (fp16)
__device__ __half g_hs [MAX_T * D_FF];          // shared L1 activations (fp16)
__device__ __half g_xh [MAX_T * D_MODEL];       // fp16 x
__device__ __half g_w1h[N_EXP * D_FF * D_MODEL];
__device__ __half g_w2h[N_EXP * D_MODEL * D_FF];
__device__ __half g_ws1h[D_FF * D_MODEL];
__device__ __half g_ws2h[D_MODEL * D_FF];

// ---------------- helpers -------------------------------------------------------
__device__ __forceinline__ uint32_t smem_u32(const void* p) {
    uint32_t a;
    asm("{ .reg .u64 t; cvta.to.shared.u64 t, %1; cvt.u32.u64 %0, t; }" : "=r"(a) : "l"(p));
    return a;
}
__device__ __forceinline__ uint32_t lds32(uint32_t a) {
    uint32_t v; asm("ld.shared.b32 %0, [%1];" : "=r"(v) : "r"(a)); return v;
}

#define CP_ASYNC16(dst, src, sz) \
    asm volatile("cp.async.cg.shared.global [%0], [%1], 16, %2;" \
                 :: "r"(dst), "l"(src), "r"(sz))
#define CP_COMMIT() asm volatile("cp.async.commit_group;" ::: "memory")
#define CP_WAIT1()  asm volatile("cp.async.wait_group 1;" ::: "memory")

// smem byte address of (row, byte) within a tile: 128B rows, 16B-chunk XOR
// swizzle keyed on row%8 (matches the cp.async store pattern).
__device__ __forceinline__ uint32_t taddr(uint32_t base, int row, int byte) {
    return base + (uint32_t)(row * 128) + (((uint32_t)byte) ^ (((uint32_t)(row & 7)) << 4));
}

__device__ __forceinline__ void mma_f16(float* c, const uint32_t* a, const uint32_t* b) {
    asm volatile(
        "mma.sync.aligned.m16n8k16.row.col.f32.f16.f16.f32 "
        "{%0,%1,%2,%3}, {%4,%5,%6,%7}, {%8,%9}, {%0,%1,%2,%3};"
        : "+f"(c[0]), "+f"(c[1]), "+f"(c[2]), "+f"(c[3])
        : "r"(a[0]), "r"(a[1]), "r"(a[2]), "r"(a[3]), "r"(b[0]), "r"(b[1]));
}

// ---------------- small kernels -------------------------------------------------
__global__ void zero_counts_kernel() {
    if (threadIdx.x < N_EXP) g_cnt[threadIdx.x] = 0;
}

__global__ void cvt_f16_kernel(const float4* __restrict__ src,
                               uint2* __restrict__ dst, int n4) {
    int i = blockIdx.x * blockDim.x + threadIdx.x;
    if (i < n4) {
        float4 v = src[i];
        __half2 h0 = __floats2half2_rn(v.x, v.y);
        __half2 h1 = __floats2half2_rn(v.z, v.w);
        uint2 o;
        o.x = *(const uint32_t*)&h0;
        o.y = *(const uint32_t*)&h1;
        dst[i] = o;
    }
}

__global__ void gate_kernel(const float* __restrict__ x,
                            const float* __restrict__ gw, int T) {
    int warp = threadIdx.x >> 5;
    int lane = threadIdx.x & 31;
    int t = blockIdx.x * 8 + warp;
    if (t >= T) return;
    const float* xt = x + (long)t * D_MODEL;
    float acc[N_EXP];
#pragma unroll
    for (int e = 0; e < N_EXP; e++) acc[e] = 0.f;
    for (int d = lane; d < D_MODEL; d += 32) {
        float xv = xt[d];
#pragma unroll
        for (int e = 0; e < N_EXP; e++) acc[e] += xv * gw[e * D_MODEL + d];
    }
#pragma unroll
    for (int e = 0; e < N_EXP; e++)
#pragma unroll
        for (int o = 16; o; o >>= 1)
            acc[e] += __shfl_xor_sync(0xffffffffu, acc[e], o);
    if (lane == 0) {
        int e0 = 0;
#pragma unroll
        for (int e = 1; e < N_EXP; e++) if (acc[e] > acc[e0]) e0 = e;
        int e1 = (e0 == 0) ? 1 : 0;
#pragma unroll
        for (int e = 0; e < N_EXP; e++)
            if (e != e0 && acc[e] > acc[e1]) e1 = e;
        float s1 = expf(acc[e1] - acc[e0]);
        float inv = 1.f / (1.f + s1);
        g_e0[t] = e0; g_e1[t] = e1;
        g_w0[t] = inv; g_w1[t] = s1 * inv;
        atomicAdd(&g_cnt[e0], 1);
        atomicAdd(&g_cnt[e1], 1);
    }
}

__global__ void offsets_kernel() {
    int o = 0;
    for (int e = 0; e < N_EXP; e++) { g_off[e] = o; g_cur[e] = o; o += g_cnt[e]; }
    g_off[N_EXP] = o;
}

__global__ void scatter_kernel(int T) {
    int t = blockIdx.x * blockDim.x + threadIdx.x;
    if (t >= T) return;
    int p0 = atomicAdd(&g_cur[g_e0[t]], 1);
    g_tok[p0] = t; g_gw[p0] = g_w0[t];
    int p1 = atomicAdd(&g_cur[g_e1[t]], 1);
    g_tok[p1] = t; g_gw[p1] = g_w1[t];
}

// ---------------- fp16 mma.sync GEMM -------------------------------------------
// C = [relu]( A_rows @ B^T + bias );  A:[*,K] fp16 rows, B:[N,K] fp16 row-major.
// RELU_OUT: C is __half (relu + fp16 round).  ATOMIC_OUT: C fp32, gate-scaled add.
// Otherwise C fp32 plain store.
template<bool EXPERT, bool GATHER_A, bool RELU_OUT, bool ATOMIC_OUT>
__global__ __launch_bounds__(256, 1)
void hgemm_kernel(const __half* __restrict__ A,
                  const __half* __restrict__ Bb,
                  const float* __restrict__ biasb,
                  void* __restrict__ Cv,
                  int M, int K, long wstride, int bstride, int ldc) {
    int m_base, m_end;
    const __half* Bw;
    const float* bias;
    if (EXPERT) {
        int e = blockIdx.z;
        int cnt = g_cnt[e];
        if ((int)(blockIdx.y * BM) >= cnt) return;
        int off = g_off[e];
        m_base = off + blockIdx.y * BM;
        m_end  = off + cnt;
        Bw = Bb + (long)e * wstride;
        bias = biasb + (long)e * bstride;
    } else {
        m_base = blockIdx.y * BM;
        m_end  = M;
        Bw = Bb; bias = biasb;
    }
    const int n0 = blockIdx.x * BN;
    const int KC = K / BK;

    extern __shared__ char smem_raw[];
    const uint32_t smem = (smem_u32(smem_raw) + 127u) & ~127u;

    const int tid = threadIdx.x;
    const int wid = tid >> 5;
    const int lid = tid & 31;
    const int grp = lid >> 2;          // 0..7
    const int q   = lid & 3;           // 0..3
    const int warp_m = (wid & 1) * 64;
    const int warp_n = (wid >> 1) * 64;

    // gmem load map: A 1024 16B segs (4/thr), B 2048 (8/thr)
    const int seg = tid & 7;            // 16B seg in 128B row
    const int r8  = tid >> 3;           // 0..31
    int a_srcrow[4];
    uint32_t a_sz[4];
#pragma unroll
    for (int i = 0; i < 4; i++) {
        int row_local = r8 + 32 * i;
        int r = m_base + row_local;
        bool v = (r < m_end);
        int sr;
        if (GATHER_A) sr = v ? g_tok[r] : 0;
        else          sr = v ? r : 0;
        a_srcrow[i] = sr;
        a_sz[i] = v ? 16u : 0u;
    }
    const __half* bbase = Bw + (long)(n0 + r8) * K + seg * 8;

    auto load_stage = [&](int s, int chunk) {
        uint32_t aB = smem + s * STAGE_BYTES;
        uint32_t bB = aB + A_BYTES;
        long ko = (long)chunk * BK;
#pragma unroll
        for (int i = 0; i < 4; i++) {
            int row_local = r8 + 32 * i;
            uint32_t dst = taddr(aB, row_local, seg * 16);
            CP_ASYNC16(dst, A + (long)a_srcrow[i] * K + seg * 8 + ko, a_sz[i]);
        }
#pragma unroll
        for (int j = 0; j < 8; j++) {
            int row_local = r8 + 32 * j;
            uint32_t dst = taddr(bB, row_local, seg * 16);
            CP_ASYNC16(dst, bbase + j * 32L * K + ko, 16u);
        }
    };

    float acc[4][8][4];
#pragma unroll
    for (int mt = 0; mt < 4; mt++)
#pragma unroll
        for (int nt = 0; nt < 8; nt++)
#pragma unroll
            for (int i = 0; i < 4; i++) acc[mt][nt][i] = 0.f;

#pragma unroll
    for (int p = 0; p < STAGES - 1; p++) { load_stage(p, p); CP_COMMIT(); }

    for (int kc = 0; kc < KC; kc++) {
        CP_WAIT1();
        __syncthreads();
        int nc = kc + STAGES - 1;
        if (nc < KC) load_stage(nc % STAGES, nc);
        CP_COMMIT();

        uint32_t aS = smem + (kc % STAGES) * STAGE_BYTES;
        uint32_t bS = aS + A_BYTES;
#pragma unroll
        for (int ks = 0; ks < 4; ks++) {
            const int kqb = ks * 32;           // byte offset of this k16 step
            uint32_t afr[4][4], bfr[8][2];
#pragma unroll
            for (int mt = 0; mt < 4; mt++) {
                int r0 = warp_m + mt * 16 + grp;
                afr[mt][0] = lds32(taddr(aS, r0,     kqb + 4 * q));
                afr[mt][1] = lds32(taddr(aS, r0 + 8, kqb + 4 * q));
                afr[mt][2] = lds32(taddr(aS, r0,     kqb + 4 * q + 16));
                afr[mt][3] = lds32(taddr(aS, r0 + 8, kqb + 4 * q + 16));
            }
#pragma unroll
            for (int nt = 0; nt < 8; nt++) {
                int n = warp_n + nt * 8 + grp;
                bfr[nt][0] = lds32(taddr(bS, n, kqb + 4 * q));
                bfr[nt][1] = lds32(taddr(bS, n, kqb + 4 * q + 16));
            }
#pragma unroll
            for (int mt = 0; mt < 4; mt++)
#pragma unroll
                for (int nt = 0; nt < 8; nt++)
                    mma_f16(acc[mt][nt], afr[mt], bfr[nt]);
        }
    }

    // ---- epilogue ----
#pragma unroll
    for (int mt = 0; mt < 4; mt++) {
#pragma unroll
        for (int half = 0; half < 2; half++) {
            int r = m_base + warp_m + mt * 16 + grp + half * 8;
            if (r >= m_end) continue;
            if (RELU_OUT) {
                __half* crow = (__half*)Cv + (long)r * ldc;
#pragma unroll
                for (int nt = 0; nt < 8; nt++) {
                    int cn = n0 + warp_n + nt * 8 + 2 * q;
                    float v0 = acc[mt][nt][half * 2 + 0] + bias[cn];
                    float v1 = acc[mt][nt][half * 2 + 1] + bias[cn + 1];
                    __half2 o = __floats2half2_rn(fmaxf(v0, 0.f), fmaxf(v1, 0.f));
                    *(__half2*)(crow + cn) = o;
                }
            } else if (ATOMIC_OUT) {
                int tok = g_tok[r];
                float sc = g_gw[r];
                float* crow = (float*)Cv + (long)tok * ldc;
#pragma unroll
                for (int nt = 0; nt < 8; nt++) {
                    int cn = n0 + warp_n + nt * 8 + 2 * q;
                    atomicAdd(crow + cn + 0, sc * (acc[mt][nt][half * 2 + 0] + bias[cn]));
                    atomicAdd(crow + cn + 1, sc * (acc[mt][nt][half * 2 + 1] + bias[cn + 1]));
                }
            } else {
                float* crow = (float*)Cv + (long)r * ldc;
#pragma unroll
                for (int nt = 0; nt < 8; nt++) {
                    int cn = n0 + warp_n + nt * 8 + 2 * q;
                    float2 o;
                    o.x = acc[mt][nt][half * 2 + 0] + bias[cn];
                    o.y = acc[mt][nt][half * 2 + 1] + bias[cn + 1];
                    *(float2*)(crow + cn) = o;
                }
            }
        }
    }
}

// ---------------- launch --------------------------------------------------------
extern "C" void kernel_launch(void* const* d_in, const int* in_sizes, int n_in,
                              void* d_out, int out_size) {
    const float* x      = (const float*)d_in[0];
    const float* gate_w = (const float*)d_in[1];
    const float* w1     = (const float*)d_in[2];
    const float* b1     = (const float*)d_in[3];
    const float* w2     = (const float*)d_in[4];
    const float* b2     = (const float*)d_in[5];
    const float* ws1    = (const float*)d_in[6];
    const float* bs1    = (const float*)d_in[7];
    const float* ws2    = (const float*)d_in[8];
    const float* bs2    = (const float*)d_in[9];
    float* out = (float*)d_out;
    int T = in_sizes[0] / D_MODEL;   // 8192

    __half *h, *hs, *xh, *w1h, *w2h, *ws1h, *ws2h;
    cudaGetSymbolAddress((void**)&h,    g_h);
    cudaGetSymbolAddress((void**)&hs,   g_hs);
    cudaGetSymbolAddress((void**)&xh,   g_xh);
    cudaGetSymbolAddress((void**)&w1h,  g_w1h);
    cudaGetSymbolAddress((void**)&w2h,  g_w2h);
    cudaGetSymbolAddress((void**)&ws1h, g_ws1h);
    cudaGetSymbolAddress((void**)&ws2h, g_ws2h);

    cudaFuncSetAttribute(hgemm_kernel<false, false, true,  false>,
                         cudaFuncAttributeMaxDynamicSharedMemorySize, SMEM_ALLOC);
    cudaFuncSetAttribute(hgemm_kernel<false, false, false, false>,
                         cudaFuncAttributeMaxDynamicSharedMemorySize, SMEM_ALLOC);
    cudaFuncSetAttribute(hgemm_kernel<true,  true,  true,  false>,
                         cudaFuncAttributeMaxDynamicSharedMemorySize, SMEM_ALLOC);
    cudaFuncSetAttribute(hgemm_kernel<true,  false, false, true >,
                         cudaFuncAttributeMaxDynamicSharedMemorySize, SMEM_ALLOC);

    // fp16 RN pre-conversion
    auto cvt = [&](const float* s, __half* d, long n) {
        int n4 = (int)(n / 4);
        cvt_f16_kernel<<<(n4 + 255) / 256, 256>>>((const float4*)s, (uint2*)d, n4);
    };
    cvt(x,   xh,   (long)T * D_MODEL);
    cvt(w1,  w1h,  (long)N_EXP * D_FF * D_MODEL);
    cvt(w2,  w2h,  (long)N_EXP * D_MODEL * D_FF);
    cvt(ws1, ws1h, (long)D_FF * D_MODEL);
    cvt(ws2, ws2h, (long)D_MODEL * D_FF);

    // routing (fp32 gate for exact expert selection)
    zero_counts_kernel<<<1, 32>>>();
    gate_kernel<<<(T + 7) / 8, 256>>>(x, gate_w, T);
    offsets_kernel<<<1, 1>>>();
    scatter_kernel<<<(T + 255) / 256, 256>>>(T);

    // layer 1 (relu, fp16 outputs)
    hgemm_kernel<false, false, true, false>
        <<<dim3(D_FF / BN, T / BM, 1), 256, SMEM_ALLOC>>>(
            xh, ws1h, bs1, hs, T, D_MODEL, 0, 0, D_FF);
    hgemm_kernel<true, true, true, false>
        <<<dim3(D_FF / BN, 2 * T / BM, N_EXP), 256, SMEM_ALLOC>>>(
            xh, w1h, b1, h, 0, D_MODEL, (long)D_FF * D_MODEL, D_FF, D_FF);

    // layer 2: shared writes base, routed atomically accumulates
    hgemm_kernel<false, false, false, false>
        <<<dim3(D_MODEL / BN, T / BM, 1), 256, SMEM_ALLOC>>>(
            hs, ws2h, bs2, out, T, D_FF, 0, 0, D_MODEL);
    hgemm_kernel<true, false, false, true>
        <<<dim3(D_MODEL / BN, 2 * T / BM, N_EXP), 256, SMEM_ALLOC>>>(
            h, w2h, b2, out, 0, D_FF, (long)D_MODEL * D_FF, D_MODEL, D_MODEL);
}

// round 6
// speedup vs baseline: 6.7796x; 1.1469x over previous
#include <cuda_runtime.h>
#include <cuda_fp16.h>
#include <cstdint>

#define D_MODEL 1024
#define D_FF    2048
#define N_EXP   8
#define MAX_T   8192
#define T_CONST 8192

#define BM 128
#define BN 128
#define BK 64                                   // halves of K per stage (128B row)
#define STAGES 3
#define A_BYTES (BM * 128)                      // 16384
#define B_BYTES (BN * 128)                      // 16384
#define STAGE_BYTES (A_BYTES + B_BYTES)         // 32768
#define SMEM_ALLOC (STAGES * STAGE_BYTES + 128) // 98432

// ---------------- device globals ----------------------------------------------
__device__ int    g_cnt[N_EXP + 1];
__device__ int    g_off[N_EXP + 2];
__device__ int    g_cur[N_EXP];
__device__ int    g_e0[MAX_T], g_e1[MAX_T];
__device__ float  g_w0[MAX_T], g_w1[MAX_T];
__device__ int    g_tok[3 * MAX_T];
__device__ float  g_gw [3 * MAX_T];
__device__ __half g_h  [3 * MAX_T * D_FF];      // L1 activations (routed 2T + shared T)
__device__ __half g_xh [MAX_T * D_MODEL];
__device__ __half g_w1h[N_EXP * D_FF * D_MODEL];
__device__ __half g_w2h[N_EXP * D_MODEL * D_FF];
__device__ __half g_ws1h[D_FF * D_MODEL];
__device__ __half g_ws2h[D_MODEL * D_FF];

// ---------------- helpers -------------------------------------------------------
__device__ __forceinline__ uint32_t smem_u32(const void* p) {
    uint32_t a;
    asm("{ .reg .u64 t; cvta.to.shared.u64 t, %1; cvt.u32.u64 %0, t; }" : "=r"(a) : "l"(p));
    return a;
}
__device__ __forceinline__ uint32_t lds32(uint32_t a) {
    uint32_t v; asm("ld.shared.b32 %0, [%1];" : "=r"(v) : "r"(a)); return v;
}

#define CP_ASYNC16(dst, src, sz) \
    asm volatile("cp.async.cg.shared.global [%0], [%1], 16, %2;" \
                 :: "r"(dst), "l"(src), "r"(sz))
#define CP_COMMIT() asm volatile("cp.async.commit_group;" ::: "memory")
#define CP_WAIT1()  asm volatile("cp.async.wait_group 1;" ::: "memory")

// smem byte address: 128B rows, 16B-chunk XOR swizzle keyed on row%8
__device__ __forceinline__ uint32_t taddr(uint32_t base, int row, int byte) {
    return base + (uint32_t)(row * 128) + (((uint32_t)byte) ^ (((uint32_t)(row & 7)) << 4));
}

__device__ __forceinline__ void mma_f16(float* c, const uint32_t* a, const uint32_t* b) {
    asm volatile(
        "mma.sync.aligned.m16n8k16.row.col.f32.f16.f16.f32 "
        "{%0,%1,%2,%3}, {%4,%5,%6,%7}, {%8,%9}, {%0,%1,%2,%3};"
        : "+f"(c[0]), "+f"(c[1]), "+f"(c[2]), "+f"(c[3])
        : "r"(a[0]), "r"(a[1]), "r"(a[2]), "r"(a[3]), "r"(b[0]), "r"(b[1]));
}

// ---------------- small kernels -------------------------------------------------
__global__ void zero_counts_kernel() {
    if (threadIdx.x < N_EXP) g_cnt[threadIdx.x] = 0;
}

// fused: convert one token row of x to fp16 AND compute gate top-2 (fp32 exact)
__global__ void gate_cvtx_kernel(const float* __restrict__ x,
                                 const float* __restrict__ gw, int T) {
    int warp = threadIdx.x >> 5;
    int lane = threadIdx.x & 31;
    int t = blockIdx.x * 8 + warp;
    if (t >= T) return;
    const float4* xt4 = (const float4*)(x + (long)t * D_MODEL);
    uint2* xo = (uint2*)(g_xh + (long)t * D_MODEL);
    const float4* gw4 = (const float4*)gw;
    float acc[N_EXP];
#pragma unroll
    for (int e = 0; e < N_EXP; e++) acc[e] = 0.f;
#pragma unroll
    for (int i = 0; i < 8; i++) {
        int f = lane + 32 * i;                  // float4 index within row (256 total)
        float4 v = xt4[f];
        __half2 h0 = __floats2half2_rn(v.x, v.y);
        __half2 h1 = __floats2half2_rn(v.z, v.w);
        uint2 o; o.x = *(const uint32_t*)&h0; o.y = *(const uint32_t*)&h1;
        xo[f] = o;
#pragma unroll
        for (int e = 0; e < N_EXP; e++) {
            float4 g = gw4[e * 256 + f];
            acc[e] += v.x * g.x + v.y * g.y + v.z * g.z + v.w * g.w;
        }
    }
#pragma unroll
    for (int e = 0; e < N_EXP; e++)
#pragma unroll
        for (int o = 16; o; o >>= 1)
            acc[e] += __shfl_xor_sync(0xffffffffu, acc[e], o);
    if (lane == 0) {
        int e0 = 0;
#pragma unroll
        for (int e = 1; e < N_EXP; e++) if (acc[e] > acc[e0]) e0 = e;
        int e1 = (e0 == 0) ? 1 : 0;
#pragma unroll
        for (int e = 0; e < N_EXP; e++)
            if (e != e0 && acc[e] > acc[e1]) e1 = e;
        float s1 = expf(acc[e1] - acc[e0]);
        float inv = 1.f / (1.f + s1);
        g_e0[t] = e0; g_e1[t] = e1;
        g_w0[t] = inv; g_w1[t] = s1 * inv;
        atomicAdd(&g_cnt[e0], 1);
        atomicAdd(&g_cnt[e1], 1);
    }
}

__global__ void offsets_kernel(int T) {
    int o = 0;
    for (int e = 0; e < N_EXP; e++) { g_off[e] = o; g_cur[e] = o; o += g_cnt[e]; }
    g_off[N_EXP] = o;              // == 2T
    g_cnt[N_EXP] = T;              // shared "expert"
    g_off[N_EXP + 1] = o + T;
}

__global__ void scatter_kernel(int T) {
    int t = blockIdx.x * blockDim.x + threadIdx.x;
    if (t >= T) return;
    int p0 = atomicAdd(&g_cur[g_e0[t]], 1);
    g_tok[p0] = t; g_gw[p0] = g_w0[t];
    int p1 = atomicAdd(&g_cur[g_e1[t]], 1);
    g_tok[p1] = t; g_gw[p1] = g_w1[t];
    g_tok[2 * T + t] = t; g_gw[2 * T + t] = 1.f;   // shared-expert slot
}

// one kernel converts w1, w2, ws1, ws2 (compile-time segment bounds)
#define W1N4  (N_EXP * D_FF * D_MODEL / 4)
#define W2N4  (N_EXP * D_MODEL * D_FF / 4)
#define WS1N4 (D_FF * D_MODEL / 4)
#define WS2N4 (D_MODEL * D_FF / 4)
#define TOTN4 (W1N4 + W2N4 + WS1N4 + WS2N4)

__global__ void cvt_all_kernel(const float4* __restrict__ w1,
                               const float4* __restrict__ w2,
                               const float4* __restrict__ ws1,
                               const float4* __restrict__ ws2) {
    int i = blockIdx.x * blockDim.x + threadIdx.x;
    if (i >= TOTN4) return;
    const float4* s; uint2* d; int j;
    if (i < W1N4)                      { s = w1;  d = (uint2*)g_w1h;  j = i; }
    else if (i < W1N4 + W2N4)          { s = w2;  d = (uint2*)g_w2h;  j = i - W1N4; }
    else if (i < W1N4 + W2N4 + WS1N4)  { s = ws1; d = (uint2*)g_ws1h; j = i - W1N4 - W2N4; }
    else                               { s = ws2; d = (uint2*)g_ws2h; j = i - W1N4 - W2N4 - WS1N4; }
    float4 v = s[j];
    __half2 h0 = __floats2half2_rn(v.x, v.y);
    __half2 h1 = __floats2half2_rn(v.z, v.w);
    uint2 o; o.x = *(const uint32_t*)&h0; o.y = *(const uint32_t*)&h1;
    d[j] = o;
}

// ---------------- fp16 mma.sync GEMM (128x128 tile, 2 CTAs/SM) ------------------
// C = [relu]( A_rows @ B^T + bias ). EXPERT: blockIdx.z in 0..NZ-1, z==N_EXP uses
// shared-expert weights. GATHER_A: row via g_tok. RELU_OUT: half out. ATOMIC_OUT:
// fp32 gate-scaled atomic accumulate into token rows.
template<bool EXPERT, bool GATHER_A, bool RELU_OUT, bool ATOMIC_OUT>
__global__ __launch_bounds__(256, 2)
void hgemm_kernel(const __half* __restrict__ A,
                  const __half* __restrict__ Bb,
                  const float* __restrict__ biasb,
                  const __half* __restrict__ Bsh,
                  const float* __restrict__ biassh,
                  void* __restrict__ Cv,
                  int M, int K, long wstride, int bstride, int ldc) {
    int m_base, m_end;
    const __half* Bw;
    const float* bias;
    if (EXPERT) {
        int e = blockIdx.z;
        int cnt = g_cnt[e];
        if ((int)(blockIdx.y * BM) >= cnt) return;
        int off = g_off[e];
        m_base = off + blockIdx.y * BM;
        m_end  = off + cnt;
        if (e == N_EXP) { Bw = Bsh; bias = biassh; }
        else            { Bw = Bb + (long)e * wstride; bias = biasb + (long)e * bstride; }
    } else {
        m_base = blockIdx.y * BM;
        m_end  = M;
        Bw = Bb; bias = biasb;
    }
    const int n0 = blockIdx.x * BN;
    const int KC = K / BK;

    extern __shared__ char smem_raw[];
    const uint32_t smem = (smem_u32(smem_raw) + 127u) & ~127u;

    const int tid = threadIdx.x;
    const int wid = tid >> 5;
    const int lid = tid & 31;
    const int grp = lid >> 2;          // 0..7
    const int q   = lid & 3;           // 0..3
    const int warp_m = (wid & 1) * 64;     // 2 warps in M
    const int warp_n = (wid >> 1) * 32;    // 4 warps in N

    // gmem load map: A 1024 16B segs (4/thr), B 1024 (4/thr)
    const int seg = tid & 7;            // 16B seg in 128B row
    const int r8  = tid >> 3;           // 0..31
    const __half* aptr[4];
    uint32_t a_sz[4];
#pragma unroll
    for (int i = 0; i < 4; i++) {
        int row_local = r8 + 32 * i;
        int r = m_base + row_local;
        bool v = (r < m_end);
        int sr;
        if (GATHER_A) sr = v ? g_tok[r] : 0;
        else          sr = v ? r : 0;
        aptr[i] = A + (long)sr * K + seg * 8;
        a_sz[i] = v ? 16u : 0u;
    }
    const __half* bbase = Bw + (long)(n0 + r8) * K + seg * 8;

    auto load_stage = [&](int s, int chunk) {
        uint32_t aB = smem + s * STAGE_BYTES;
        uint32_t bB = aB + A_BYTES;
        long ko = (long)chunk * BK;
#pragma unroll
        for (int i = 0; i < 4; i++) {
            int row_local = r8 + 32 * i;
            CP_ASYNC16(taddr(aB, row_local, seg * 16), aptr[i] + ko, a_sz[i]);
        }
#pragma unroll
        for (int j = 0; j < 4; j++) {
            int row_local = r8 + 32 * j;
            CP_ASYNC16(taddr(bB, row_local, seg * 16), bbase + j * 32L * K + ko, 16u);
        }
    };

    float acc[4][4][4];
#pragma unroll
    for (int mt = 0; mt < 4; mt++)
#pragma unroll
        for (int nt = 0; nt < 4; nt++)
#pragma unroll
            for (int i = 0; i < 4; i++) acc[mt][nt][i] = 0.f;

#pragma unroll
    for (int p = 0; p < STAGES - 1; p++) { load_stage(p, p); CP_COMMIT(); }

    for (int kc = 0; kc < KC; kc++) {
        CP_WAIT1();
        __syncthreads();
        int nc = kc + STAGES - 1;
        if (nc < KC) load_stage(nc % STAGES, nc);
        CP_COMMIT();

        uint32_t aS = smem + (kc % STAGES) * STAGE_BYTES;
        uint32_t bS = aS + A_BYTES;
#pragma unroll
        for (int ks = 0; ks < 4; ks++) {
            const int kqb = ks * 32;            // byte offset of this k16 step
            uint32_t afr[4][4], bfr[4][2];
#pragma unroll
            for (int mt = 0; mt < 4; mt++) {
                int r0 = warp_m + mt * 16 + grp;
                afr[mt][0] = lds32(taddr(aS, r0,     kqb + 4 * q));
                afr[mt][1] = lds32(taddr(aS, r0 + 8, kqb + 4 * q));
                afr[mt][2] = lds32(taddr(aS, r0,     kqb + 4 * q + 16));
                afr[mt][3] = lds32(taddr(aS, r0 + 8, kqb + 4 * q + 16));
            }
#pragma unroll
            for (int nt = 0; nt < 4; nt++) {
                int n = warp_n + nt * 8 + grp;
                bfr[nt][0] = lds32(taddr(bS, n, kqb + 4 * q));
                bfr[nt][1] = lds32(taddr(bS, n, kqb + 4 * q + 16));
            }
#pragma unroll
            for (int mt = 0; mt < 4; mt++)
#pragma unroll
                for (int nt = 0; nt < 4; nt++)
                    mma_f16(acc[mt][nt], afr[mt], bfr[nt]);
        }
    }

    // ---- epilogue ----
#pragma unroll
    for (int mt = 0; mt < 4; mt++) {
#pragma unroll
        for (int half = 0; half < 2; half++) {
            int r = m_base + warp_m + mt * 16 + grp + half * 8;
            if (r >= m_end) continue;
            if (RELU_OUT) {
                __half* crow = (__half*)Cv + (long)r * ldc;
#pragma unroll
                for (int nt = 0; nt < 4; nt++) {
                    int cn = n0 + warp_n + nt * 8 + 2 * q;
                    float v0 = acc[mt][nt][half * 2 + 0] + bias[cn];
                    float v1 = acc[mt][nt][half * 2 + 1] + bias[cn + 1];
                    __half2 o = __floats2half2_rn(fmaxf(v0, 0.f), fmaxf(v1, 0.f));
                    *(__half2*)(crow + cn) = o;
                }
            } else if (ATOMIC_OUT) {
                int tok = g_tok[r];
                float sc = g_gw[r];
                float* crow = (float*)Cv + (long)tok * ldc;
#pragma unroll
                for (int nt = 0; nt < 4; nt++) {
                    int cn = n0 + warp_n + nt * 8 + 2 * q;
                    atomicAdd(crow + cn + 0, sc * (acc[mt][nt][half * 2 + 0] + bias[cn]));
                    atomicAdd(crow + cn + 1, sc * (acc[mt][nt][half * 2 + 1] + bias[cn + 1]));
                }
            } else {
                float* crow = (float*)Cv + (long)r * ldc;
#pragma unroll
                for (int nt = 0; nt < 4; nt++) {
                    int cn = n0 + warp_n + nt * 8 + 2 * q;
                    float2 o;
                    o.x = acc[mt][nt][half * 2 + 0] + bias[cn];
                    o.y = acc[mt][nt][half * 2 + 1] + bias[cn + 1];
                    *(float2*)(crow + cn) = o;
                }
            }
        }
    }
}

// ---------------- launch --------------------------------------------------------
extern "C" void kernel_launch(void* const* d_in, const int* in_sizes, int n_in,
                              void* d_out, int out_size) {
    const float* x      = (const float*)d_in[0];
    const float* gate_w = (const float*)d_in[1];
    const float* w1     = (const float*)d_in[2];
    const float* b1     = (const float*)d_in[3];
    const float* w2     = (const float*)d_in[4];
    const float* b2     = (const float*)d_in[5];
    const float* ws1    = (const float*)d_in[6];
    const float* bs1    = (const float*)d_in[7];
    const float* ws2    = (const float*)d_in[8];
    const float* bs2    = (const float*)d_in[9];
    float* out = (float*)d_out;
    int T = in_sizes[0] / D_MODEL;   // 8192

    __half *h, *xh, *w1h, *w2h, *ws1h, *ws2h;
    cudaGetSymbolAddress((void**)&h,    g_h);
    cudaGetSymbolAddress((void**)&xh,   g_xh);
    cudaGetSymbolAddress((void**)&w1h,  g_w1h);
    cudaGetSymbolAddress((void**)&w2h,  g_w2h);
    cudaGetSymbolAddress((void**)&ws1h, g_ws1h);
    cudaGetSymbolAddress((void**)&ws2h, g_ws2h);

    cudaFuncSetAttribute(hgemm_kernel<true,  true,  true,  false>,
                         cudaFuncAttributeMaxDynamicSharedMemorySize, SMEM_ALLOC);
    cudaFuncSetAttribute(hgemm_kernel<false, false, false, false>,
                         cudaFuncAttributeMaxDynamicSharedMemorySize, SMEM_ALLOC);
    cudaFuncSetAttribute(hgemm_kernel<true,  false, false, true >,
                         cudaFuncAttributeMaxDynamicSharedMemorySize, SMEM_ALLOC);

    // routing + x conversion (fused)
    zero_counts_kernel<<<1, 32>>>();
    gate_cvtx_kernel<<<(T + 7) / 8, 256>>>(x, gate_w, T);
    offsets_kernel<<<1, 1>>>(T);
    scatter_kernel<<<(T + 255) / 256, 256>>>(T);

    // weight conversion (single launch)
    cvt_all_kernel<<<(TOTN4 + 255) / 256, 256>>>(
        (const float4*)w1, (const float4*)w2, (const float4*)ws1, (const float4*)ws2);

    // layer 1: unified routed + shared (expert 8), relu -> fp16 h
    hgemm_kernel<true, true, true, false>
        <<<dim3(D_FF / BN, T / BM, N_EXP + 1), 256, SMEM_ALLOC>>>(
            xh, w1h, b1, ws1h, bs1, h, 0, D_MODEL,
            (long)D_FF * D_MODEL, D_FF, D_FF);

    // layer 2: shared expert writes out base (slots 2T..3T are identity tokens)
    hgemm_kernel<false, false, false, false>
        <<<dim3(D_MODEL / BN, T / BM, 1), 256, SMEM_ALLOC>>>(
            h + (long)2 * T * D_FF, ws2h, bs2, nullptr, nullptr, out,
            T, D_FF, 0, 0, D_MODEL);

    // layer 2: routed experts atomically accumulate
    hgemm_kernel<true, false, false, true>
        <<<dim3(D_MODEL / BN, T / BM, N_EXP), 256, SMEM_ALLOC>>>(
            h, w2h, b2, nullptr, nullptr, out, 0, D_FF,
            (long)D_MODEL * D_FF, D_MODEL, D_MODEL);
}